// round 14
// baseline (speedup 1.0000x reference)
#include <cuda_runtime.h>
#include <math.h>

#define NN 4096
#define DD 256
#define KK 32
#define LL 4
#define TT 100
#define PP 64
#define BB 32
#define CIN2 320           // feat + pos (time-embed hoisted to bias)
#define NSTATE 5

// ---------------- scratch (device globals; no allocations) ----------------
__device__ float g_in[NN * CIN2];
__device__ float g_cat[NN * 2 * DD];     // [h | msg] (ld 512)
__device__ float g_hs[NN * DD];
__device__ float g_states[NN * NSTATE * DD];
__device__ float g_out[NN * DD];
__device__ int   g_idx[NN * KK];
__device__ float g_ed[NN * KK];
__device__ float g_rbf[NN * KK * BB];
__device__ float g_sx[NN], g_sy[NN], g_sz[NN];
__device__ float g_wfull[LL * 2 * DD * DD];   // [Wcat_top_l ; Wconv_l@Wcat_bot_l]
__device__ float g_tvec[DD];                  // temb @ W_in[0:100]

// ---------------- helpers ----------------
__device__ __forceinline__ float f2tf(float x) {
    unsigned r;
    asm("cvt.rna.tf32.f32 %0, %1;" : "=r"(r) : "f"(x));
    return __uint_as_float(r);
}
__device__ __forceinline__ void split2(float f, unsigned& hi, unsigned& lo) {
    float h = f2tf(f);
    float l = f2tf(f - h);
    hi = __float_as_uint(h);
    lo = __float_as_uint(l);
}
__device__ __forceinline__ void mma_tf32(float& d0, float& d1, float& d2, float& d3,
                                         unsigned a0, unsigned a1, unsigned a2, unsigned a3,
                                         unsigned b0, unsigned b1) {
    asm volatile(
        "mma.sync.aligned.m16n8k8.row.col.f32.tf32.tf32.f32 "
        "{%0,%1,%2,%3}, {%4,%5,%6,%7}, {%8,%9}, {%0,%1,%2,%3};"
        : "+f"(d0), "+f"(d1), "+f"(d2), "+f"(d3)
        : "r"(a0), "r"(a1), "r"(a2), "r"(a3), "r"(b0), "r"(b1));
}

// ---------------- prologue: copy Wcat_top halves into g_wfull ----------------
__global__ void copyw_kernel(const float* __restrict__ Wcat, float* __restrict__ wfull) {
    int t = blockIdx.x * 256 + threadIdx.x;
    if (t >= LL * DD * DD) return;
    int l = t / (DD * DD);
    int rem = t - l * (DD * DD);
    wfull[(size_t)l * 2 * DD * DD + rem] = Wcat[(size_t)l * 2 * DD * DD + rem];
}

// ---------------- prologue: tvec = time_embed(t) @ W_in[0:100,:] ----------------
__global__ void tvec_kernel(const float* __restrict__ W_in,
                            const float* __restrict__ tptr,
                            float* __restrict__ tvec) {
    int c = threadIdx.x;
    float t = *tptr;
    float acc = 0.0f;
    for (int k = 0; k < TT; k++) {
        float d = (t - (float)k * (1.0f / 99.0f)) * 99.0f;
        float a = fabsf(d);
        float e = 0.0f;
        if (a < 1.0f) {
            float cc = cospif(0.5f * d);
            e = cc * cc;
        }
        acc += e * W_in[(size_t)k * DD + c];
    }
    tvec[c] = acc;
}

// ---------------- input build: [feat | pos] only (320 cols) ----------------
__global__ void build_in_kernel(const float* __restrict__ feat,
                                const float* __restrict__ pos,
                                float* __restrict__ out) {
    int i = blockIdx.x;
    for (int c = threadIdx.x; c < CIN2; c += blockDim.x) {
        float v = (c < DD) ? feat[i * DD + c] : pos[i * PP + (c - DD)];
        out[(size_t)i * CIN2 + c] = v;
    }
}

// ---------------- SoA coord transpose ----------------
__global__ void soa_kernel(const float* __restrict__ coord,
                           float* __restrict__ gx, float* __restrict__ gy,
                           float* __restrict__ gz) {
    int j = blockIdx.x * 256 + threadIdx.x;
    if (j < NN) {
        gx[j] = coord[j * 3 + 0];
        gy[j] = coord[j * 3 + 1];
        gz[j] = coord[j * 3 + 2];
    }
}

// ---------------- kNN (R5 block version — frozen) ----------------
__global__ __launch_bounds__(256) void knn_kernel(const float* __restrict__ gx,
                                                  const float* __restrict__ gy,
                                                  const float* __restrict__ gz,
                                                  int* __restrict__ idx_out,
                                                  float* __restrict__ ed_out) {
    __shared__ float dist[NN];
    __shared__ float wv[8];
    __shared__ int wi[8];
    __shared__ int s_sel;
    int i = blockIdx.x;
    int tid = threadIdx.x;
    int lane = tid & 31;
    int warp = tid >> 5;
    float cx = gx[i], cy = gy[i], cz = gz[i];
    float v = 3.4e38f;
    int bi = 0x7FFFFFFF;
    for (int j = tid; j < NN; j += 256) {
        float dx = cx - gx[j];
        float dy = cy - gy[j];
        float dz = cz - gz[j];
        float d2 = dx * dx + dy * dy + dz * dz;
        if (j == i) d2 += 1e9f;
        dist[j] = d2;
        if (d2 < v) { v = d2; bi = j; }
    }
    __syncthreads();
    for (int kk = 0; kk < KK; kk++) {
        float rv = v; int rb = bi;
        #pragma unroll
        for (int o = 16; o > 0; o >>= 1) {
            float ov = __shfl_down_sync(0xFFFFFFFFu, rv, o);
            int ob = __shfl_down_sync(0xFFFFFFFFu, rb, o);
            if (ov < rv || (ov == rv && ob < rb)) { rv = ov; rb = ob; }
        }
        if (lane == 0) { wv[warp] = rv; wi[warp] = rb; }
        __syncthreads();
        if (warp == 0) {
            float v2 = (lane < 8) ? wv[lane] : 3.4e38f;
            int b2 = (lane < 8) ? wi[lane] : 0x7FFFFFFF;
            #pragma unroll
            for (int o = 4; o > 0; o >>= 1) {
                float ov = __shfl_down_sync(0xFFFFFFFFu, v2, o);
                int ob = __shfl_down_sync(0xFFFFFFFFu, b2, o);
                if (ov < v2 || (ov == v2 && ob < b2)) { v2 = ov; b2 = ob; }
            }
            if (lane == 0) {
                idx_out[i * KK + kk] = b2;
                ed_out[i * KK + kk] = sqrtf(fmaxf(v2, 1e-12f));
                dist[b2] = 3.4e38f;
                s_sel = b2;
            }
        }
        __syncthreads();
        int b = s_sel;
        if ((b & 255) == tid) {
            v = 3.4e38f; bi = 0x7FFFFFFF;
            for (int j = tid; j < NN; j += 256) {
                float d2 = dist[j];
                if (d2 < v) { v = d2; bi = j; }
            }
        }
    }
}

// ---------------- gaussian RBF ----------------
__global__ void rbf_kernel(const float* __restrict__ ed, float* __restrict__ rbf) {
    int t = blockIdx.x * blockDim.x + threadIdx.x;
    if (t >= NN * KK * BB) return;
    int b = t & (BB - 1);
    int ik = t >> 5;
    float d = ed[ik];
    float c = 32.0f * (float)b * (1.0f / 31.0f);
    float x = d - c;
    rbf[t] = expf(-x * x);
}

// ================= split-tf32 GEMM(+LN), 16x256 tile (256 blocks) =================
#define GBK 32
#define AST 36
#define BST 264

template <bool DO_LN>
__global__ __launch_bounds__(256) void gemm_ln_kernel(const float* __restrict__ A,
                                                      const float* __restrict__ Bm,
                                                      float* __restrict__ C,
                                                      int Kd, int lda, int ldc,
                                                      const float* __restrict__ mask,
                                                      float* __restrict__ states,
                                                      int state_col,
                                                      const float* __restrict__ pre_bias,
                                                      long offA, long offB, long offC) {
    __shared__ float As[16 * AST];
    __shared__ float Bs[32 * BST];
    A += (long)blockIdx.y * offA;
    Bm += (long)blockIdx.y * offB;
    C += (long)blockIdx.y * offC;
    int tid = threadIdx.x;
    int bm = blockIdx.x * 16;
    int warp = tid >> 5, lane = tid & 31;
    int gid = lane >> 2, tig = lane & 3;

    const float* Abase = A + (size_t)bm * lda;

    // A tile 16x32 = 128 float4: threads 0..127 only
    bool aload = tid < 128;
    int ar = tid >> 3;            // 0..15 for tid<128
    int ac4 = (tid & 7) * 4;

    float4 avr;
    float4 bvr[8];

    auto load_tile = [&](int k0) {
        if (aload) {
            const float* p = Abase + (size_t)ar * lda + k0 + ac4;
            if (k0 + ac4 + 4 <= Kd) {
                avr = *reinterpret_cast<const float4*>(p);
            } else {
                float x0 = (k0 + ac4 + 0 < Kd) ? p[0] : 0.0f;
                float x1 = (k0 + ac4 + 1 < Kd) ? p[1] : 0.0f;
                float x2 = (k0 + ac4 + 2 < Kd) ? p[2] : 0.0f;
                float x3 = (k0 + ac4 + 3 < Kd) ? p[3] : 0.0f;
                avr = make_float4(x0, x1, x2, x3);
            }
        }
        #pragma unroll
        for (int it = 0; it < 8; it++) {
            int idx = it * 256 + tid;
            int r = idx >> 6;
            int c4 = (idx & 63) * 4;
            if (k0 + r < Kd) {
                bvr[it] = *reinterpret_cast<const float4*>(Bm + (size_t)(k0 + r) * DD + c4);
            } else {
                bvr[it] = make_float4(0.f, 0.f, 0.f, 0.f);
            }
        }
    };
    auto store_tile = [&]() {
        if (aload) *reinterpret_cast<float4*>(&As[ar * AST + ac4]) = avr;
        #pragma unroll
        for (int it = 0; it < 8; it++) {
            int idx = it * 256 + tid;
            int r = idx >> 6;
            int c4 = (idx & 63) * 4;
            *reinterpret_cast<float4*>(&Bs[r * BST + c4]) = bvr[it];
        }
    };

    float cf[4][4];
    #pragma unroll
    for (int nt = 0; nt < 4; nt++)
        #pragma unroll
        for (int q = 0; q < 4; q++) cf[nt][q] = 0.0f;

    load_tile(0);
    store_tile();
    __syncthreads();

    for (int k0 = 0;;) {
        int knext = k0 + GBK;
        bool has_next = knext < Kd;
        if (has_next) load_tile(knext);
        #pragma unroll
        for (int ks = 0; ks < 4; ks++) {
            int kc = ks * 8 + tig;
            unsigned ahi[4], alo[4];
            split2(As[gid * AST + kc],            ahi[0], alo[0]);
            split2(As[(gid + 8) * AST + kc],      ahi[1], alo[1]);
            split2(As[gid * AST + kc + 4],        ahi[2], alo[2]);
            split2(As[(gid + 8) * AST + kc + 4],  ahi[3], alo[3]);
            unsigned bhi[4][2], blo[4][2];
            #pragma unroll
            for (int nt = 0; nt < 4; nt++) {
                int cb = warp * 32 + nt * 8 + gid;
                split2(Bs[(ks * 8 + tig) * BST + cb],     bhi[nt][0], blo[nt][0]);
                split2(Bs[(ks * 8 + tig + 4) * BST + cb], bhi[nt][1], blo[nt][1]);
            }
            #pragma unroll
            for (int nt = 0; nt < 4; nt++) {
                mma_tf32(cf[nt][0], cf[nt][1], cf[nt][2], cf[nt][3],
                         ahi[0], ahi[1], ahi[2], ahi[3],
                         bhi[nt][0], bhi[nt][1]);
                mma_tf32(cf[nt][0], cf[nt][1], cf[nt][2], cf[nt][3],
                         ahi[0], ahi[1], ahi[2], ahi[3],
                         blo[nt][0], blo[nt][1]);
                mma_tf32(cf[nt][0], cf[nt][1], cf[nt][2], cf[nt][3],
                         alo[0], alo[1], alo[2], alo[3],
                         bhi[nt][0], bhi[nt][1]);
            }
        }
        if (!has_next) break;
        __syncthreads();
        store_tile();
        __syncthreads();
        k0 = knext;
    }

    if (!DO_LN) {
        if ((ldc & 1) == 0) {
            #pragma unroll
            for (int nt = 0; nt < 4; nt++) {
                int r0 = bm + gid;
                int c = warp * 32 + nt * 8 + tig * 2;
                *reinterpret_cast<float2*>(C + (size_t)r0 * ldc + c) =
                    make_float2(cf[nt][0], cf[nt][1]);
                *reinterpret_cast<float2*>(C + (size_t)(r0 + 8) * ldc + c) =
                    make_float2(cf[nt][2], cf[nt][3]);
            }
        } else {
            #pragma unroll
            for (int nt = 0; nt < 4; nt++) {
                int r0 = bm + gid;
                int c = warp * 32 + nt * 8 + tig * 2;
                C[(size_t)r0 * ldc + c]           = cf[nt][0];
                C[(size_t)r0 * ldc + c + 1]       = cf[nt][1];
                C[(size_t)(r0 + 8) * ldc + c]     = cf[nt][2];
                C[(size_t)(r0 + 8) * ldc + c + 1] = cf[nt][3];
            }
        }
        return;
    }

    // ---- LN epilogue (16 rows; 16 threads per row) ----
    __syncthreads();
    #pragma unroll
    for (int nt = 0; nt < 4; nt++) {
        int c = warp * 32 + nt * 8 + tig * 2;
        Bs[gid * BST + c]           = cf[nt][0];
        Bs[gid * BST + c + 1]       = cf[nt][1];
        Bs[(gid + 8) * BST + c]     = cf[nt][2];
        Bs[(gid + 8) * BST + c + 1] = cf[nt][3];
    }
    __syncthreads();

    int row = tid >> 4;          // 0..15
    int sub = tid & 15;          // 0..15
    int i = bm + row;
    float mk = mask ? mask[i] : 1.0f;
    float s = 0.0f, s2 = 0.0f;
    #pragma unroll
    for (int j = 0; j < 16; j++) {
        int c = sub + j * 16;
        float x = Bs[row * BST + c];
        if (pre_bias) x += mk * pre_bias[c];
        s += x;
        s2 += x * x;
    }
    #pragma unroll
    for (int o = 8; o > 0; o >>= 1) {
        s  += __shfl_xor_sync(0xFFFFFFFFu, s, o);
        s2 += __shfl_xor_sync(0xFFFFFFFFu, s2, o);
    }
    float mean = s * (1.0f / DD);
    float var = s2 * (1.0f / DD) - mean * mean;
    float scale = rsqrtf(var + 1e-5f);
    float* yrow = C + (size_t)i * ldc;
    float* srow = states ? states + (size_t)i * (NSTATE * DD) + state_col * DD : nullptr;
    #pragma unroll
    for (int j = 0; j < 16; j++) {
        int c = sub + j * 16;
        float x = Bs[row * BST + c];
        if (pre_bias) x += mk * pre_bias[c];
        float y = (x - mean) * scale * mk;
        yrow[c] = y;
        if (srow) srow[c] = y;
    }
}

// ================= tensor-core message kernel (frozen; out with ldo) =================
__global__ __launch_bounds__(256) void msg_mma_kernel(const float* __restrict__ h,
                                                      const int* __restrict__ idx,
                                                      const float* __restrict__ rbf,
                                                      const float* __restrict__ Wrad,
                                                      float* __restrict__ out, int ldo) {
    __shared__ float As[32 * AST];
    __shared__ float Bs[32 * BST];
    __shared__ int js[KK];
    int i = blockIdx.x;
    int tid = threadIdx.x;
    int warp = tid >> 5, lane = tid & 31;
    int gid = lane >> 2, tig = lane & 3;

    {
        int r = tid >> 3;
        int b4 = (tid & 7) * 4;
        *reinterpret_cast<float4*>(&As[r * AST + b4]) =
            *reinterpret_cast<const float4*>(rbf + (size_t)i * (KK * BB) + r * BB + b4);
    }
    #pragma unroll
    for (int it = 0; it < 8; it++) {
        int idx2 = it * 256 + tid;
        int r = idx2 >> 6;
        int c4 = (idx2 & 63) * 4;
        *reinterpret_cast<float4*>(&Bs[r * BST + c4]) =
            *reinterpret_cast<const float4*>(Wrad + (size_t)r * DD + c4);
    }
    if (tid < KK) js[tid] = idx[i * KK + tid];
    __syncthreads();

    float cf[2][4][4];
    #pragma unroll
    for (int mt = 0; mt < 2; mt++)
        #pragma unroll
        for (int nt = 0; nt < 4; nt++)
            #pragma unroll
            for (int q = 0; q < 4; q++) cf[mt][nt][q] = 0.0f;

    #pragma unroll
    for (int ks = 0; ks < 4; ks++) {
        int kc = ks * 8 + tig;
        unsigned ahi[2][4], alo[2][4];
        #pragma unroll
        for (int mt = 0; mt < 2; mt++) {
            int r = gid + mt * 16;
            split2(As[r * AST + kc],            ahi[mt][0], alo[mt][0]);
            split2(As[(r + 8) * AST + kc],      ahi[mt][1], alo[mt][1]);
            split2(As[r * AST + kc + 4],        ahi[mt][2], alo[mt][2]);
            split2(As[(r + 8) * AST + kc + 4],  ahi[mt][3], alo[mt][3]);
        }
        unsigned bhi[4][2], blo[4][2];
        #pragma unroll
        for (int nt = 0; nt < 4; nt++) {
            int cb = warp * 32 + nt * 8 + gid;
            split2(Bs[(ks * 8 + tig) * BST + cb],     bhi[nt][0], blo[nt][0]);
            split2(Bs[(ks * 8 + tig + 4) * BST + cb], bhi[nt][1], blo[nt][1]);
        }
        #pragma unroll
        for (int mt = 0; mt < 2; mt++)
            #pragma unroll
            for (int nt = 0; nt < 4; nt++) {
                mma_tf32(cf[mt][nt][0], cf[mt][nt][1], cf[mt][nt][2], cf[mt][nt][3],
                         ahi[mt][0], ahi[mt][1], ahi[mt][2], ahi[mt][3],
                         bhi[nt][0], bhi[nt][1]);
                mma_tf32(cf[mt][nt][0], cf[mt][nt][1], cf[mt][nt][2], cf[mt][nt][3],
                         ahi[mt][0], ahi[mt][1], ahi[mt][2], ahi[mt][3],
                         blo[nt][0], blo[nt][1]);
                mma_tf32(cf[mt][nt][0], cf[mt][nt][1], cf[mt][nt][2], cf[mt][nt][3],
                         alo[mt][0], alo[mt][1], alo[mt][2], alo[mt][3],
                         bhi[nt][0], bhi[nt][1]);
            }
    }
    __syncthreads();

    #pragma unroll
    for (int it = 0; it < 8; it++) {
        int idx2 = it * 256 + tid;
        int r = idx2 >> 6;
        int c4 = (idx2 & 63) * 4;
        int j = js[r];
        *reinterpret_cast<float4*>(&Bs[r * BST + c4]) =
            *reinterpret_cast<const float4*>(h + (size_t)j * DD + c4);
    }
    __syncthreads();

    float sacc[4][2];
    #pragma unroll
    for (int nt = 0; nt < 4; nt++) { sacc[nt][0] = 0.0f; sacc[nt][1] = 0.0f; }
    #pragma unroll
    for (int mt = 0; mt < 2; mt++) {
        int r = gid + mt * 16;
        #pragma unroll
        for (int nt = 0; nt < 4; nt++) {
            int c = warp * 32 + nt * 8 + tig * 2;
            sacc[nt][0] += cf[mt][nt][0] * Bs[r * BST + c];
            sacc[nt][1] += cf[mt][nt][1] * Bs[r * BST + c + 1];
            sacc[nt][0] += cf[mt][nt][2] * Bs[(r + 8) * BST + c];
            sacc[nt][1] += cf[mt][nt][3] * Bs[(r + 8) * BST + c + 1];
        }
    }
    #pragma unroll
    for (int o = 4; o <= 16; o <<= 1) {
        #pragma unroll
        for (int nt = 0; nt < 4; nt++) {
            sacc[nt][0] += __shfl_xor_sync(0xFFFFFFFFu, sacc[nt][0], o);
            sacc[nt][1] += __shfl_xor_sync(0xFFFFFFFFu, sacc[nt][1], o);
        }
    }
    if (gid == 0) {
        #pragma unroll
        for (int nt = 0; nt < 4; nt++) {
            int c = warp * 32 + nt * 8 + tig * 2;
            out[(size_t)i * ldo + c]     = sacc[nt][0] * (1.0f / KK);
            out[(size_t)i * ldo + c + 1] = sacc[nt][1] * (1.0f / KK);
        }
    }
}

// ---------------- coord head ----------------
__global__ void coord_out_kernel(const float* __restrict__ out,
                                 const float* __restrict__ Wc,
                                 float* __restrict__ dout) {
    int i = blockIdx.x;
    int w = threadIdx.x >> 5, lane = threadIdx.x & 31;
    float s = 0.0f;
    for (int d = lane; d < DD; d += 32) s += out[i * DD + d] * Wc[d * 3 + w];
    #pragma unroll
    for (int o = 16; o > 0; o >>= 1) s += __shfl_down_sync(0xFFFFFFFFu, s, o);
    if (lane == 0) dout[(size_t)i * (DD + 3) + DD + w] = s;
}

// ---------------- host launcher ----------------
static void* symaddr(const void* s) {
    void* p = nullptr;
    cudaGetSymbolAddress(&p, s);
    return p;
}

extern "C" void kernel_launch(void* const* d_in, const int* in_sizes, int n_in,
                              void* d_out, int out_size) {
    const float* feat   = (const float*)d_in[0];
    const float* coord  = (const float*)d_in[1];
    const float* mask   = (const float*)d_in[2];
    const float* tptr   = (const float*)d_in[3];
    const float* pos    = (const float*)d_in[4];
    const float* W_in   = (const float*)d_in[5];
    const float* W_self = (const float*)d_in[6];
    const float* W_rad  = (const float*)d_in[7];
    const float* W_conv = (const float*)d_in[8];
    const float* W_cat  = (const float*)d_in[9];
    const float* W_out  = (const float*)d_in[10];
    const float* W_noise= (const float*)d_in[11];
    const float* W_coord= (const float*)d_in[12];
    float* out = (float*)d_out;

    float* p_in     = (float*)symaddr(g_in);
    float* p_cat    = (float*)symaddr(g_cat);
    float* p_hs     = (float*)symaddr(g_hs);
    float* p_states = (float*)symaddr(g_states);
    float* p_out    = (float*)symaddr(g_out);
    int*   p_idx    = (int*)symaddr(g_idx);
    float* p_ed     = (float*)symaddr(g_ed);
    float* p_rbf    = (float*)symaddr(g_rbf);
    float* p_sx     = (float*)symaddr(g_sx);
    float* p_sy     = (float*)symaddr(g_sy);
    float* p_sz     = (float*)symaddr(g_sz);
    float* p_wfull  = (float*)symaddr(g_wfull);
    float* p_tvec   = (float*)symaddr(g_tvec);

    static cudaStream_t s2 = nullptr;
    static cudaEvent_t ev_fork = nullptr, ev_join = nullptr;
    static bool ok = false;
    if (!ok) {
        cudaError_t e1 = cudaStreamCreateWithFlags(&s2, cudaStreamNonBlocking);
        cudaError_t e2 = cudaEventCreateWithFlags(&ev_fork, cudaEventDisableTiming);
        cudaError_t e3 = cudaEventCreateWithFlags(&ev_join, cudaEventDisableTiming);
        ok = (e1 == cudaSuccess && e2 == cudaSuccess && e3 == cudaSuccess);
    }

    int gg = NN / 16;   // 256 blocks

    bool overlap = ok;
    if (overlap) {
        cudaEventRecord(ev_fork, 0);
        cudaStreamWaitEvent(s2, ev_fork, 0);
        copyw_kernel<<<(LL * DD * DD + 255) / 256, 256, 0, s2>>>(W_cat, p_wfull);
        gemm_ln_kernel<false><<<dim3(DD / 16, LL), 256, 0, s2>>>(
            W_conv, W_cat + (size_t)DD * DD, p_wfull + (size_t)DD * DD,
            DD, DD, DD, nullptr, nullptr, 0, nullptr,
            (long)DD * DD, (long)2 * DD * DD, (long)2 * DD * DD);
        soa_kernel<<<NN / 256, 256, 0, s2>>>(coord, p_sx, p_sy, p_sz);
        knn_kernel<<<NN, 256, 0, s2>>>(p_sx, p_sy, p_sz, p_idx, p_ed);
        rbf_kernel<<<(NN * KK * BB + 255) / 256, 256, 0, s2>>>(p_ed, p_rbf);
        cudaEventRecord(ev_join, s2);
    } else {
        copyw_kernel<<<(LL * DD * DD + 255) / 256, 256>>>(W_cat, p_wfull);
        gemm_ln_kernel<false><<<dim3(DD / 16, LL), 256>>>(
            W_conv, W_cat + (size_t)DD * DD, p_wfull + (size_t)DD * DD,
            DD, DD, DD, nullptr, nullptr, 0, nullptr,
            (long)DD * DD, (long)2 * DD * DD, (long)2 * DD * DD);
        soa_kernel<<<NN / 256, 256>>>(coord, p_sx, p_sy, p_sz);
        knn_kernel<<<NN, 256>>>(p_sx, p_sy, p_sz, p_idx, p_ed);
        rbf_kernel<<<(NN * KK * BB + 255) / 256, 256>>>(p_ed, p_rbf);
    }

    // ---- main chain (overlaps with side stream) ----
    tvec_kernel<<<1, DD>>>(W_in, tptr, p_tvec);
    build_in_kernel<<<NN, 128>>>(feat, pos, p_in);
    gemm_ln_kernel<true><<<gg, 256>>>(p_in, W_in + (size_t)TT * DD, p_cat,
                                      CIN2, CIN2, 2 * DD, mask, p_states, 0,
                                      p_tvec, 0, 0, 0);
    gemm_ln_kernel<true><<<gg, 256>>>(p_cat, W_self, p_hs, DD, 2 * DD, DD,
                                      nullptr, nullptr, 0, nullptr, 0, 0, 0);
    if (overlap) cudaStreamWaitEvent(0, ev_join, 0);

    for (int l = 0; l < LL; l++) {
        const float* Wself_l = W_self + (size_t)l * DD * DD;
        const float* Wrad_l  = W_rad  + (size_t)l * BB * DD;
        const float* Wfull_l = p_wfull + (size_t)l * 2 * DD * DD;

        if (l > 0) {
            gemm_ln_kernel<true><<<gg, 256>>>(p_cat, Wself_l, p_hs, DD, 2 * DD, DD,
                                              nullptr, nullptr, 0, nullptr, 0, 0, 0);
        }
        msg_mma_kernel<<<NN, 256>>>(p_hs, p_idx, p_rbf, Wrad_l, p_cat + DD, 2 * DD);
        gemm_ln_kernel<true><<<gg, 256>>>(p_cat, Wfull_l, p_cat, 2 * DD, 2 * DD, 2 * DD,
                                          mask, p_states, l + 1, nullptr, 0, 0, 0);
    }

    gemm_ln_kernel<false><<<gg, 256>>>(p_states, W_out, p_out, NSTATE * DD, NSTATE * DD, DD,
                                       nullptr, nullptr, 0, nullptr, 0, 0, 0);
    gemm_ln_kernel<false><<<gg, 256>>>(p_out, W_noise, out, DD, DD, DD + 3,
                                       nullptr, nullptr, 0, nullptr, 0, 0, 0);
    coord_out_kernel<<<NN, 96>>>(p_out, W_coord, out);
}

// round 15
// speedup vs baseline: 1.1597x; 1.1597x over previous
#include <cuda_runtime.h>
#include <math.h>

#define NN 4096
#define DD 256
#define KK 32
#define LL 4
#define TT 100
#define PP 64
#define BB 32
#define CIN2 320           // feat + pos (time-embed hoisted to bias)
#define NSTATE 5

// ---------------- scratch (device globals; no allocations) ----------------
__device__ float g_in[NN * CIN2];
__device__ float g_cat[NN * 2 * DD];     // [h | msg] (ld 512)
__device__ float g_hs[NN * DD];
__device__ float g_t0[NN * DD];          // cat-top partial
__device__ float g_states[NN * NSTATE * DD];
__device__ float g_out[NN * DD];
__device__ int   g_idx[NN * KK];
__device__ float g_ed[NN * KK];
__device__ float g_rbf[NN * KK * BB];
__device__ float g_sx[NN], g_sy[NN], g_sz[NN];
__device__ float g_wbot[LL * DD * DD];   // Wconv_l @ Wcat_bot_l
__device__ float g_tvec[DD];             // temb @ W_in[0:100]

// ---------------- helpers ----------------
__device__ __forceinline__ float f2tf(float x) {
    unsigned r;
    asm("cvt.rna.tf32.f32 %0, %1;" : "=r"(r) : "f"(x));
    return __uint_as_float(r);
}
__device__ __forceinline__ void split2(float f, unsigned& hi, unsigned& lo) {
    float h = f2tf(f);
    float l = f2tf(f - h);
    hi = __float_as_uint(h);
    lo = __float_as_uint(l);
}
__device__ __forceinline__ void mma_tf32(float& d0, float& d1, float& d2, float& d3,
                                         unsigned a0, unsigned a1, unsigned a2, unsigned a3,
                                         unsigned b0, unsigned b1) {
    asm volatile(
        "mma.sync.aligned.m16n8k8.row.col.f32.tf32.tf32.f32 "
        "{%0,%1,%2,%3}, {%4,%5,%6,%7}, {%8,%9}, {%0,%1,%2,%3};"
        : "+f"(d0), "+f"(d1), "+f"(d2), "+f"(d3)
        : "r"(a0), "r"(a1), "r"(a2), "r"(a3), "r"(b0), "r"(b1));
}

// ---------------- prologue: tvec = time_embed(t) @ W_in[0:100,:] ----------------
__global__ void tvec_kernel(const float* __restrict__ W_in,
                            const float* __restrict__ tptr,
                            float* __restrict__ tvec) {
    int c = threadIdx.x;
    float t = *tptr;
    float acc = 0.0f;
    for (int k = 0; k < TT; k++) {
        float d = (t - (float)k * (1.0f / 99.0f)) * 99.0f;
        float a = fabsf(d);
        float e = 0.0f;
        if (a < 1.0f) {
            float cc = cospif(0.5f * d);
            e = cc * cc;
        }
        acc += e * W_in[(size_t)k * DD + c];
    }
    tvec[c] = acc;
}

// ---------------- input build: [feat | pos] only (320 cols) ----------------
__global__ void build_in_kernel(const float* __restrict__ feat,
                                const float* __restrict__ pos,
                                float* __restrict__ out) {
    int i = blockIdx.x;
    for (int c = threadIdx.x; c < CIN2; c += blockDim.x) {
        float v = (c < DD) ? feat[i * DD + c] : pos[i * PP + (c - DD)];
        out[(size_t)i * CIN2 + c] = v;
    }
}

// ---------------- SoA coord transpose ----------------
__global__ void soa_kernel(const float* __restrict__ coord,
                           float* __restrict__ gx, float* __restrict__ gy,
                           float* __restrict__ gz) {
    int j = blockIdx.x * 256 + threadIdx.x;
    if (j < NN) {
        gx[j] = coord[j * 3 + 0];
        gy[j] = coord[j * 3 + 1];
        gz[j] = coord[j * 3 + 2];
    }
}

// ---------------- kNN (R5 block version — frozen) ----------------
__global__ __launch_bounds__(256) void knn_kernel(const float* __restrict__ gx,
                                                  const float* __restrict__ gy,
                                                  const float* __restrict__ gz,
                                                  int* __restrict__ idx_out,
                                                  float* __restrict__ ed_out) {
    __shared__ float dist[NN];
    __shared__ float wv[8];
    __shared__ int wi[8];
    __shared__ int s_sel;
    int i = blockIdx.x;
    int tid = threadIdx.x;
    int lane = tid & 31;
    int warp = tid >> 5;
    float cx = gx[i], cy = gy[i], cz = gz[i];
    float v = 3.4e38f;
    int bi = 0x7FFFFFFF;
    for (int j = tid; j < NN; j += 256) {
        float dx = cx - gx[j];
        float dy = cy - gy[j];
        float dz = cz - gz[j];
        float d2 = dx * dx + dy * dy + dz * dz;
        if (j == i) d2 += 1e9f;
        dist[j] = d2;
        if (d2 < v) { v = d2; bi = j; }
    }
    __syncthreads();
    for (int kk = 0; kk < KK; kk++) {
        float rv = v; int rb = bi;
        #pragma unroll
        for (int o = 16; o > 0; o >>= 1) {
            float ov = __shfl_down_sync(0xFFFFFFFFu, rv, o);
            int ob = __shfl_down_sync(0xFFFFFFFFu, rb, o);
            if (ov < rv || (ov == rv && ob < rb)) { rv = ov; rb = ob; }
        }
        if (lane == 0) { wv[warp] = rv; wi[warp] = rb; }
        __syncthreads();
        if (warp == 0) {
            float v2 = (lane < 8) ? wv[lane] : 3.4e38f;
            int b2 = (lane < 8) ? wi[lane] : 0x7FFFFFFF;
            #pragma unroll
            for (int o = 4; o > 0; o >>= 1) {
                float ov = __shfl_down_sync(0xFFFFFFFFu, v2, o);
                int ob = __shfl_down_sync(0xFFFFFFFFu, b2, o);
                if (ov < v2 || (ov == v2 && ob < b2)) { v2 = ov; b2 = ob; }
            }
            if (lane == 0) {
                idx_out[i * KK + kk] = b2;
                ed_out[i * KK + kk] = sqrtf(fmaxf(v2, 1e-12f));
                dist[b2] = 3.4e38f;
                s_sel = b2;
            }
        }
        __syncthreads();
        int b = s_sel;
        if ((b & 255) == tid) {
            v = 3.4e38f; bi = 0x7FFFFFFF;
            for (int j = tid; j < NN; j += 256) {
                float d2 = dist[j];
                if (d2 < v) { v = d2; bi = j; }
            }
        }
    }
}

// ---------------- gaussian RBF ----------------
__global__ void rbf_kernel(const float* __restrict__ ed, float* __restrict__ rbf) {
    int t = blockIdx.x * blockDim.x + threadIdx.x;
    if (t >= NN * KK * BB) return;
    int b = t & (BB - 1);
    int ik = t >> 5;
    float d = ed[ik];
    float c = 32.0f * (float)b * (1.0f / 31.0f);
    float x = d - c;
    rbf[t] = expf(-x * x);
}

// ================= split-tf32 GEMM(+LN), 32x256 tile (frozen R13 config) =================
// Optional pre-LN bias (mask[i]*pre_bias[c]) and pre-LN accumulator (pre_acc[i*DD+c]).
#define GBK 32
#define AST 36
#define BST 264

template <bool DO_LN>
__global__ __launch_bounds__(256) void gemm_ln_kernel(const float* __restrict__ A,
                                                      const float* __restrict__ Bm,
                                                      float* __restrict__ C,
                                                      int Kd, int lda, int ldc,
                                                      const float* __restrict__ mask,
                                                      float* __restrict__ states,
                                                      int state_col,
                                                      const float* __restrict__ pre_bias,
                                                      const float* __restrict__ pre_acc,
                                                      long offA, long offB, long offC) {
    __shared__ float As[32 * AST];
    __shared__ float Bs[32 * BST];
    A += (long)blockIdx.y * offA;
    Bm += (long)blockIdx.y * offB;
    C += (long)blockIdx.y * offC;
    int tid = threadIdx.x;
    int bm = blockIdx.x * 32;
    int warp = tid >> 5, lane = tid & 31;
    int gid = lane >> 2, tig = lane & 3;

    const float* Abase = A + (size_t)bm * lda;

    float4 avr;
    float4 bvr[8];
    int ar = tid >> 3;
    int ac4 = (tid & 7) * 4;

    auto load_tile = [&](int k0) {
        const float* p = Abase + (size_t)ar * lda + k0 + ac4;
        if (k0 + ac4 + 4 <= Kd) {
            avr = *reinterpret_cast<const float4*>(p);
        } else {
            float x0 = (k0 + ac4 + 0 < Kd) ? p[0] : 0.0f;
            float x1 = (k0 + ac4 + 1 < Kd) ? p[1] : 0.0f;
            float x2 = (k0 + ac4 + 2 < Kd) ? p[2] : 0.0f;
            float x3 = (k0 + ac4 + 3 < Kd) ? p[3] : 0.0f;
            avr = make_float4(x0, x1, x2, x3);
        }
        #pragma unroll
        for (int it = 0; it < 8; it++) {
            int idx = it * 256 + tid;
            int r = idx >> 6;
            int c4 = (idx & 63) * 4;
            if (k0 + r < Kd) {
                bvr[it] = *reinterpret_cast<const float4*>(Bm + (size_t)(k0 + r) * DD + c4);
            } else {
                bvr[it] = make_float4(0.f, 0.f, 0.f, 0.f);
            }
        }
    };
    auto store_tile = [&]() {
        *reinterpret_cast<float4*>(&As[ar * AST + ac4]) = avr;
        #pragma unroll
        for (int it = 0; it < 8; it++) {
            int idx = it * 256 + tid;
            int r = idx >> 6;
            int c4 = (idx & 63) * 4;
            *reinterpret_cast<float4*>(&Bs[r * BST + c4]) = bvr[it];
        }
    };

    float cf[2][4][4];
    #pragma unroll
    for (int mt = 0; mt < 2; mt++)
        #pragma unroll
        for (int nt = 0; nt < 4; nt++)
            #pragma unroll
            for (int q = 0; q < 4; q++) cf[mt][nt][q] = 0.0f;

    load_tile(0);
    store_tile();
    __syncthreads();

    for (int k0 = 0;;) {
        int knext = k0 + GBK;
        bool has_next = knext < Kd;
        if (has_next) load_tile(knext);
        #pragma unroll
        for (int ks = 0; ks < 4; ks++) {
            int kc = ks * 8 + tig;
            unsigned ahi[2][4], alo[2][4];
            #pragma unroll
            for (int mt = 0; mt < 2; mt++) {
                int r = gid + mt * 16;
                split2(As[r * AST + kc],            ahi[mt][0], alo[mt][0]);
                split2(As[(r + 8) * AST + kc],      ahi[mt][1], alo[mt][1]);
                split2(As[r * AST + kc + 4],        ahi[mt][2], alo[mt][2]);
                split2(As[(r + 8) * AST + kc + 4],  ahi[mt][3], alo[mt][3]);
            }
            unsigned bhi[4][2], blo[4][2];
            #pragma unroll
            for (int nt = 0; nt < 4; nt++) {
                int cb = warp * 32 + nt * 8 + gid;
                split2(Bs[(ks * 8 + tig) * BST + cb],     bhi[nt][0], blo[nt][0]);
                split2(Bs[(ks * 8 + tig + 4) * BST + cb], bhi[nt][1], blo[nt][1]);
            }
            #pragma unroll
            for (int mt = 0; mt < 2; mt++)
                #pragma unroll
                for (int nt = 0; nt < 4; nt++) {
                    mma_tf32(cf[mt][nt][0], cf[mt][nt][1], cf[mt][nt][2], cf[mt][nt][3],
                             ahi[mt][0], ahi[mt][1], ahi[mt][2], ahi[mt][3],
                             bhi[nt][0], bhi[nt][1]);
                    mma_tf32(cf[mt][nt][0], cf[mt][nt][1], cf[mt][nt][2], cf[mt][nt][3],
                             ahi[mt][0], ahi[mt][1], ahi[mt][2], ahi[mt][3],
                             blo[nt][0], blo[nt][1]);
                    mma_tf32(cf[mt][nt][0], cf[mt][nt][1], cf[mt][nt][2], cf[mt][nt][3],
                             alo[mt][0], alo[mt][1], alo[mt][2], alo[mt][3],
                             bhi[nt][0], bhi[nt][1]);
                }
        }
        if (!has_next) break;
        __syncthreads();
        store_tile();
        __syncthreads();
        k0 = knext;
    }

    if (!DO_LN) {
        if ((ldc & 1) == 0) {
            #pragma unroll
            for (int mt = 0; mt < 2; mt++)
                #pragma unroll
                for (int nt = 0; nt < 4; nt++) {
                    int r0 = bm + gid + mt * 16;
                    int c = warp * 32 + nt * 8 + tig * 2;
                    *reinterpret_cast<float2*>(C + (size_t)r0 * ldc + c) =
                        make_float2(cf[mt][nt][0], cf[mt][nt][1]);
                    *reinterpret_cast<float2*>(C + (size_t)(r0 + 8) * ldc + c) =
                        make_float2(cf[mt][nt][2], cf[mt][nt][3]);
                }
        } else {
            #pragma unroll
            for (int mt = 0; mt < 2; mt++)
                #pragma unroll
                for (int nt = 0; nt < 4; nt++) {
                    int r0 = bm + gid + mt * 16;
                    int c = warp * 32 + nt * 8 + tig * 2;
                    C[(size_t)r0 * ldc + c]           = cf[mt][nt][0];
                    C[(size_t)r0 * ldc + c + 1]       = cf[mt][nt][1];
                    C[(size_t)(r0 + 8) * ldc + c]     = cf[mt][nt][2];
                    C[(size_t)(r0 + 8) * ldc + c + 1] = cf[mt][nt][3];
                }
        }
        return;
    }

    // ---- LN epilogue ----
    __syncthreads();
    #pragma unroll
    for (int mt = 0; mt < 2; mt++)
        #pragma unroll
        for (int nt = 0; nt < 4; nt++) {
            int r = gid + mt * 16;
            int c = warp * 32 + nt * 8 + tig * 2;
            Bs[r * BST + c]           = cf[mt][nt][0];
            Bs[r * BST + c + 1]       = cf[mt][nt][1];
            Bs[(r + 8) * BST + c]     = cf[mt][nt][2];
            Bs[(r + 8) * BST + c + 1] = cf[mt][nt][3];
        }
    __syncthreads();

    int row = tid >> 3;
    int sub = tid & 7;
    int i = bm + row;
    float mk = mask ? mask[i] : 1.0f;
    const float* arow = pre_acc ? pre_acc + (size_t)i * DD : nullptr;
    float s = 0.0f, s2 = 0.0f;
    #pragma unroll
    for (int j = 0; j < 32; j++) {
        int c = sub + j * 8;
        float x = Bs[row * BST + c];
        if (pre_bias) x += mk * pre_bias[c];
        if (arow) x += arow[c];
        s += x;
        s2 += x * x;
    }
    #pragma unroll
    for (int o = 4; o > 0; o >>= 1) {
        s  += __shfl_xor_sync(0xFFFFFFFFu, s, o);
        s2 += __shfl_xor_sync(0xFFFFFFFFu, s2, o);
    }
    float mean = s * (1.0f / DD);
    float var = s2 * (1.0f / DD) - mean * mean;
    float scale = rsqrtf(var + 1e-5f);
    float* yrow = C + (size_t)i * ldc;
    float* srow = states ? states + (size_t)i * (NSTATE * DD) + state_col * DD : nullptr;
    #pragma unroll
    for (int j = 0; j < 32; j++) {
        int c = sub + j * 8;
        float x = Bs[row * BST + c];
        if (pre_bias) x += mk * pre_bias[c];
        if (arow) x += arow[c];
        float y = (x - mean) * scale * mk;
        yrow[c] = y;
        if (srow) srow[c] = y;
    }
}

// ================= tensor-core message kernel (frozen; out with ldo) =================
__global__ __launch_bounds__(256) void msg_mma_kernel(const float* __restrict__ h,
                                                      const int* __restrict__ idx,
                                                      const float* __restrict__ rbf,
                                                      const float* __restrict__ Wrad,
                                                      float* __restrict__ out, int ldo) {
    __shared__ float As[32 * AST];
    __shared__ float Bs[32 * BST];
    __shared__ int js[KK];
    int i = blockIdx.x;
    int tid = threadIdx.x;
    int warp = tid >> 5, lane = tid & 31;
    int gid = lane >> 2, tig = lane & 3;

    {
        int r = tid >> 3;
        int b4 = (tid & 7) * 4;
        *reinterpret_cast<float4*>(&As[r * AST + b4]) =
            *reinterpret_cast<const float4*>(rbf + (size_t)i * (KK * BB) + r * BB + b4);
    }
    #pragma unroll
    for (int it = 0; it < 8; it++) {
        int idx2 = it * 256 + tid;
        int r = idx2 >> 6;
        int c4 = (idx2 & 63) * 4;
        *reinterpret_cast<float4*>(&Bs[r * BST + c4]) =
            *reinterpret_cast<const float4*>(Wrad + (size_t)r * DD + c4);
    }
    if (tid < KK) js[tid] = idx[i * KK + tid];
    __syncthreads();

    float cf[2][4][4];
    #pragma unroll
    for (int mt = 0; mt < 2; mt++)
        #pragma unroll
        for (int nt = 0; nt < 4; nt++)
            #pragma unroll
            for (int q = 0; q < 4; q++) cf[mt][nt][q] = 0.0f;

    #pragma unroll
    for (int ks = 0; ks < 4; ks++) {
        int kc = ks * 8 + tig;
        unsigned ahi[2][4], alo[2][4];
        #pragma unroll
        for (int mt = 0; mt < 2; mt++) {
            int r = gid + mt * 16;
            split2(As[r * AST + kc],            ahi[mt][0], alo[mt][0]);
            split2(As[(r + 8) * AST + kc],      ahi[mt][1], alo[mt][1]);
            split2(As[r * AST + kc + 4],        ahi[mt][2], alo[mt][2]);
            split2(As[(r + 8) * AST + kc + 4],  ahi[mt][3], alo[mt][3]);
        }
        unsigned bhi[4][2], blo[4][2];
        #pragma unroll
        for (int nt = 0; nt < 4; nt++) {
            int cb = warp * 32 + nt * 8 + gid;
            split2(Bs[(ks * 8 + tig) * BST + cb],     bhi[nt][0], blo[nt][0]);
            split2(Bs[(ks * 8 + tig + 4) * BST + cb], bhi[nt][1], blo[nt][1]);
        }
        #pragma unroll
        for (int mt = 0; mt < 2; mt++)
            #pragma unroll
            for (int nt = 0; nt < 4; nt++) {
                mma_tf32(cf[mt][nt][0], cf[mt][nt][1], cf[mt][nt][2], cf[mt][nt][3],
                         ahi[mt][0], ahi[mt][1], ahi[mt][2], ahi[mt][3],
                         bhi[nt][0], bhi[nt][1]);
                mma_tf32(cf[mt][nt][0], cf[mt][nt][1], cf[mt][nt][2], cf[mt][nt][3],
                         ahi[mt][0], ahi[mt][1], ahi[mt][2], ahi[mt][3],
                         blo[nt][0], blo[nt][1]);
                mma_tf32(cf[mt][nt][0], cf[mt][nt][1], cf[mt][nt][2], cf[mt][nt][3],
                         alo[mt][0], alo[mt][1], alo[mt][2], alo[mt][3],
                         bhi[nt][0], bhi[nt][1]);
            }
    }
    __syncthreads();

    #pragma unroll
    for (int it = 0; it < 8; it++) {
        int idx2 = it * 256 + tid;
        int r = idx2 >> 6;
        int c4 = (idx2 & 63) * 4;
        int j = js[r];
        *reinterpret_cast<float4*>(&Bs[r * BST + c4]) =
            *reinterpret_cast<const float4*>(h + (size_t)j * DD + c4);
    }
    __syncthreads();

    float sacc[4][2];
    #pragma unroll
    for (int nt = 0; nt < 4; nt++) { sacc[nt][0] = 0.0f; sacc[nt][1] = 0.0f; }
    #pragma unroll
    for (int mt = 0; mt < 2; mt++) {
        int r = gid + mt * 16;
        #pragma unroll
        for (int nt = 0; nt < 4; nt++) {
            int c = warp * 32 + nt * 8 + tig * 2;
            sacc[nt][0] += cf[mt][nt][0] * Bs[r * BST + c];
            sacc[nt][1] += cf[mt][nt][1] * Bs[r * BST + c + 1];
            sacc[nt][0] += cf[mt][nt][2] * Bs[(r + 8) * BST + c];
            sacc[nt][1] += cf[mt][nt][3] * Bs[(r + 8) * BST + c + 1];
        }
    }
    #pragma unroll
    for (int o = 4; o <= 16; o <<= 1) {
        #pragma unroll
        for (int nt = 0; nt < 4; nt++) {
            sacc[nt][0] += __shfl_xor_sync(0xFFFFFFFFu, sacc[nt][0], o);
            sacc[nt][1] += __shfl_xor_sync(0xFFFFFFFFu, sacc[nt][1], o);
        }
    }
    if (gid == 0) {
        #pragma unroll
        for (int nt = 0; nt < 4; nt++) {
            int c = warp * 32 + nt * 8 + tig * 2;
            out[(size_t)i * ldo + c]     = sacc[nt][0] * (1.0f / KK);
            out[(size_t)i * ldo + c + 1] = sacc[nt][1] * (1.0f / KK);
        }
    }
}

// ---------------- coord head ----------------
__global__ void coord_out_kernel(const float* __restrict__ out,
                                 const float* __restrict__ Wc,
                                 float* __restrict__ dout) {
    int i = blockIdx.x;
    int w = threadIdx.x >> 5, lane = threadIdx.x & 31;
    float s = 0.0f;
    for (int d = lane; d < DD; d += 32) s += out[i * DD + d] * Wc[d * 3 + w];
    #pragma unroll
    for (int o = 16; o > 0; o >>= 1) s += __shfl_down_sync(0xFFFFFFFFu, s, o);
    if (lane == 0) dout[(size_t)i * (DD + 3) + DD + w] = s;
}

// ---------------- host launcher ----------------
static void* symaddr(const void* s) {
    void* p = nullptr;
    cudaGetSymbolAddress(&p, s);
    return p;
}

extern "C" void kernel_launch(void* const* d_in, const int* in_sizes, int n_in,
                              void* d_out, int out_size) {
    const float* feat   = (const float*)d_in[0];
    const float* coord  = (const float*)d_in[1];
    const float* mask   = (const float*)d_in[2];
    const float* tptr   = (const float*)d_in[3];
    const float* pos    = (const float*)d_in[4];
    const float* W_in   = (const float*)d_in[5];
    const float* W_self = (const float*)d_in[6];
    const float* W_rad  = (const float*)d_in[7];
    const float* W_conv = (const float*)d_in[8];
    const float* W_cat  = (const float*)d_in[9];
    const float* W_out  = (const float*)d_in[10];
    const float* W_noise= (const float*)d_in[11];
    const float* W_coord= (const float*)d_in[12];
    float* out = (float*)d_out;

    float* p_in     = (float*)symaddr(g_in);
    float* p_cat    = (float*)symaddr(g_cat);
    float* p_hs     = (float*)symaddr(g_hs);
    float* p_t0     = (float*)symaddr(g_t0);
    float* p_states = (float*)symaddr(g_states);
    float* p_out    = (float*)symaddr(g_out);
    int*   p_idx    = (int*)symaddr(g_idx);
    float* p_ed     = (float*)symaddr(g_ed);
    float* p_rbf    = (float*)symaddr(g_rbf);
    float* p_sx     = (float*)symaddr(g_sx);
    float* p_sy     = (float*)symaddr(g_sy);
    float* p_sz     = (float*)symaddr(g_sz);
    float* p_wbot   = (float*)symaddr(g_wbot);
    float* p_tvec   = (float*)symaddr(g_tvec);

    static cudaStream_t s2 = nullptr;
    static cudaEvent_t ev_fork = nullptr, ev_join = nullptr;
    static cudaEvent_t evH[LL], evT[LL];
    static bool ok = false;
    if (!ok) {
        bool good = true;
        good &= cudaStreamCreateWithFlags(&s2, cudaStreamNonBlocking) == cudaSuccess;
        good &= cudaEventCreateWithFlags(&ev_fork, cudaEventDisableTiming) == cudaSuccess;
        good &= cudaEventCreateWithFlags(&ev_join, cudaEventDisableTiming) == cudaSuccess;
        for (int l = 0; l < LL; l++) {
            good &= cudaEventCreateWithFlags(&evH[l], cudaEventDisableTiming) == cudaSuccess;
            good &= cudaEventCreateWithFlags(&evT[l], cudaEventDisableTiming) == cudaSuccess;
        }
        ok = good;
    }

    int gg = NN / 32;   // 128 blocks

    bool overlap = ok;
    if (overlap) {
        // ---- fork: fused bot weights + kNN subgraph on side stream ----
        cudaEventRecord(ev_fork, 0);
        cudaStreamWaitEvent(s2, ev_fork, 0);
        // g_wbot[l] = W_conv[l] @ W_cat[l][256:512]  (batched over 4 layers)
        gemm_ln_kernel<false><<<dim3(DD / 32, LL), 256, 0, s2>>>(
            W_conv, W_cat + (size_t)DD * DD, p_wbot,
            DD, DD, DD, nullptr, nullptr, 0, nullptr, nullptr,
            (long)DD * DD, (long)2 * DD * DD, (long)DD * DD);
        soa_kernel<<<NN / 256, 256, 0, s2>>>(coord, p_sx, p_sy, p_sz);
        knn_kernel<<<NN, 256, 0, s2>>>(p_sx, p_sy, p_sz, p_idx, p_ed);
        rbf_kernel<<<(NN * KK * BB + 255) / 256, 256, 0, s2>>>(p_ed, p_rbf);
        cudaEventRecord(ev_join, s2);
    } else {
        gemm_ln_kernel<false><<<dim3(DD / 32, LL), 256>>>(
            W_conv, W_cat + (size_t)DD * DD, p_wbot,
            DD, DD, DD, nullptr, nullptr, 0, nullptr, nullptr,
            (long)DD * DD, (long)2 * DD * DD, (long)DD * DD);
        soa_kernel<<<NN / 256, 256>>>(coord, p_sx, p_sy, p_sz);
        knn_kernel<<<NN, 256>>>(p_sx, p_sy, p_sz, p_idx, p_ed);
        rbf_kernel<<<(NN * KK * BB + 255) / 256, 256>>>(p_ed, p_rbf);
    }

    // ---- main chain ----
    tvec_kernel<<<1, DD>>>(W_in, tptr, p_tvec);
    build_in_kernel<<<NN, 128>>>(feat, pos, p_in);
    // h0 = LN(in @ W_in[100:420] + mask*tvec) * mask -> cat[:, :256], states[0]
    gemm_ln_kernel<true><<<gg, 256>>>(p_in, W_in + (size_t)TT * DD, p_cat,
                                      CIN2, CIN2, 2 * DD, mask, p_states, 0,
                                      p_tvec, nullptr, 0, 0, 0);
    if (overlap) cudaEventRecord(evH[0], 0);
    // layer-0 self-interaction (idx/rbf-independent)
    gemm_ln_kernel<true><<<gg, 256>>>(p_cat, W_self, p_hs, DD, 2 * DD, DD,
                                      nullptr, nullptr, 0, nullptr, nullptr, 0, 0, 0);
    if (overlap) cudaStreamWaitEvent(0, ev_join, 0);

    for (int l = 0; l < LL; l++) {
        const float* Wself_l = W_self + (size_t)l * DD * DD;
        const float* Wrad_l  = W_rad  + (size_t)l * BB * DD;
        const float* Wtop_l  = W_cat  + (size_t)l * 2 * DD * DD;   // rows 0..255
        const float* Wbot_l  = p_wbot + (size_t)l * DD * DD;       // fused bot

        if (l > 0) {
            if (overlap) cudaEventRecord(evH[l], 0);
            gemm_ln_kernel<true><<<gg, 256>>>(p_cat, Wself_l, p_hs, DD, 2 * DD, DD,
                                              nullptr, nullptr, 0, nullptr, nullptr, 0, 0, 0);
        }
        if (overlap) {
            // side: top partial = h_l @ Wcat_top  (concurrent with self+msg)
            cudaStreamWaitEvent(s2, evH[l], 0);
            gemm_ln_kernel<false><<<gg, 256, 0, s2>>>(p_cat, Wtop_l, p_t0,
                                                      DD, 2 * DD, DD,
                                                      nullptr, nullptr, 0, nullptr, nullptr,
                                                      0, 0, 0);
            cudaEventRecord(evT[l], s2);
        }
        // msg -> cat[:, 256:512]
        msg_mma_kernel<<<NN, 256>>>(p_hs, p_idx, p_rbf, Wrad_l, p_cat + DD, 2 * DD);
        if (overlap) {
            cudaStreamWaitEvent(0, evT[l], 0);
            // h_{l+1} = LN(top_partial + msg @ Wbot) * mask
            gemm_ln_kernel<true><<<gg, 256>>>(p_cat + DD, Wbot_l, p_cat,
                                              DD, 2 * DD, 2 * DD,
                                              mask, p_states, l + 1, nullptr, p_t0, 0, 0, 0);
        } else {
            // fallback: sequential top then bot
            gemm_ln_kernel<false><<<gg, 256>>>(p_cat, Wtop_l, p_t0, DD, 2 * DD, DD,
                                               nullptr, nullptr, 0, nullptr, nullptr, 0, 0, 0);
            gemm_ln_kernel<true><<<gg, 256>>>(p_cat + DD, Wbot_l, p_cat,
                                              DD, 2 * DD, 2 * DD,
                                              mask, p_states, l + 1, nullptr, p_t0, 0, 0, 0);
        }
    }

    gemm_ln_kernel<false><<<gg, 256>>>(p_states, W_out, p_out, NSTATE * DD, NSTATE * DD, DD,
                                       nullptr, nullptr, 0, nullptr, nullptr, 0, 0, 0);
    gemm_ln_kernel<false><<<gg, 256>>>(p_out, W_noise, out, DD, DD, DD + 3,
                                       nullptr, nullptr, 0, nullptr, nullptr, 0, 0, 0);
    coord_out_kernel<<<NN, 96>>>(p_out, W_coord, out);
}